// round 17
// baseline (speedup 1.0000x reference)
#include <cuda_runtime.h>
#include <cstdint>

#define NUM_NODE 50000
#define NUM_EDGE 1600000
#define NUM_REL  512
#define DIM      64
#define SCAN_T   1024

// ---------------------------------------------------------------------------
// Device scratch (alloc-free rule: __device__ globals).
// g_count zero-init at load; gather_gemm re-zeroes per call.
// ---------------------------------------------------------------------------
__device__ int   g_count[NUM_NODE];
__device__ int   g_off[NUM_NODE + 1];
__device__ int   g_pos[NUM_EDGE];      // intra-bucket position per edge
__device__ int2  g_meta[NUM_EDGE];     // (u | r<<16 | nl<<25, w_bits)

// ---------------------------------------------------------------------------
// K1: histogram + per-edge bucket position (4 edges/thread, int4 loads)
// ---------------------------------------------------------------------------
__global__ void __launch_bounds__(256) hist_kernel(const int* __restrict__ edge_list) {
    int t  = blockIdx.x * blockDim.x + threadIdx.x;
    int e0 = t * 4;
    if (e0 >= NUM_EDGE) return;

    if (e0 + 4 <= NUM_EDGE) {
        const int4* el = (const int4*)(edge_list + (size_t)e0 * 3);
        int4 c0 = __ldg(&el[0]);   // u0 v0 r0 u1
        int4 c1 = __ldg(&el[1]);   // v1 r1 u2 v2
        int4 c2 = __ldg(&el[2]);   // r2 u3 v3 r3
        int4 p;
        p.x = atomicAdd(&g_count[c0.y], 1);
        p.y = atomicAdd(&g_count[c1.x], 1);
        p.z = atomicAdd(&g_count[c1.w], 1);
        p.w = atomicAdd(&g_count[c2.z], 1);
        *((int4*)(g_pos + e0)) = p;
    } else {
        for (int e = e0; e < NUM_EDGE; e++) {
            int v = __ldg(&edge_list[e * 3 + 1]);
            g_pos[e] = atomicAdd(&g_count[v], 1);
        }
    }
}

// ---------------------------------------------------------------------------
// K2: single-block exclusive scan, warp-coalesced two-pass
// ---------------------------------------------------------------------------
__global__ void __launch_bounds__(SCAN_T) scan_kernel() {
    __shared__ int wsum[32];
    int t    = threadIdx.x;
    int wid  = t >> 5;
    int lane = t & 31;
    const int CHW = (NUM_NODE + 31) / 32;
    int base = wid * CHW;
    int end  = min(base + CHW, NUM_NODE);

    int sum = 0;
    for (int i = base + lane; i < end; i += 32) sum += g_count[i];
    #pragma unroll
    for (int o = 16; o > 0; o >>= 1) sum += __shfl_xor_sync(0xffffffffu, sum, o);
    if (lane == 0) wsum[wid] = sum;
    __syncthreads();

    if (wid == 0) {
        int v    = wsum[lane];
        int incl = v;
        #pragma unroll
        for (int o = 1; o < 32; o <<= 1) {
            int p = __shfl_up_sync(0xffffffffu, incl, o);
            if (lane >= o) incl += p;
        }
        wsum[lane] = incl - v;
        if (lane == 31) g_off[NUM_NODE] = incl;
    }
    __syncthreads();

    int run = wsum[wid];
    for (int i0 = base; i0 < end; i0 += 32) {
        int i = i0 + lane;
        int c = (i < end) ? g_count[i] : 0;
        int incl = c;
        #pragma unroll
        for (int o = 1; o < 32; o <<= 1) {
            int p = __shfl_up_sync(0xffffffffu, incl, o);
            if (lane >= o) incl += p;
        }
        if (i < end) g_off[i] = run + incl - c;
        run += __shfl_sync(0xffffffffu, incl, 31);
    }
}

// ---------------------------------------------------------------------------
// K3: scatter packed edge meta — 4 edges/thread, vectorized loads,
// 4 independent store chains. Packs nl = v & 63 into key bits 25-30.
// ---------------------------------------------------------------------------
__global__ void __launch_bounds__(256) scatter_kernel(
    const int*   __restrict__ edge_list,
    const float* __restrict__ edge_weight)
{
    int t  = blockIdx.x * blockDim.x + threadIdx.x;
    int e0 = t * 4;
    if (e0 >= NUM_EDGE) return;

    if (e0 + 4 <= NUM_EDGE) {
        const int4* el = (const int4*)(edge_list + (size_t)e0 * 3);
        int4 c0 = __ldg(&el[0]);   // u0 v0 r0 u1
        int4 c1 = __ldg(&el[1]);   // v1 r1 u2 v2
        int4 c2 = __ldg(&el[2]);   // r2 u3 v3 r3
        int4   p = __ldg((const int4*)  (g_pos       + e0));
        float4 w = __ldg((const float4*)(edge_weight + e0));

        int s0 = __ldg(&g_off[c0.y]) + p.x;
        int s1 = __ldg(&g_off[c1.x]) + p.y;
        int s2 = __ldg(&g_off[c1.w]) + p.z;
        int s3 = __ldg(&g_off[c2.z]) + p.w;

        g_meta[s0] = make_int2(c0.x | (c0.z << 16) | ((c0.y & 63) << 25), __float_as_int(w.x));
        g_meta[s1] = make_int2(c0.w | (c1.y << 16) | ((c1.x & 63) << 25), __float_as_int(w.y));
        g_meta[s2] = make_int2(c1.z | (c2.x << 16) | ((c1.w & 63) << 25), __float_as_int(w.z));
        g_meta[s3] = make_int2(c2.y | (c2.w << 16) | ((c2.z & 63) << 25), __float_as_int(w.w));
    } else {
        for (int e = e0; e < NUM_EDGE; e++) {
            int   u = __ldg(&edge_list[e * 3 + 0]);
            int   v = __ldg(&edge_list[e * 3 + 1]);
            int   r = __ldg(&edge_list[e * 3 + 2]);
            float w = __ldg(&edge_weight[e]);
            int slot = __ldg(&g_off[v]) + __ldg(&g_pos[e]);
            g_meta[slot] = make_int2(u | (r << 16) | ((v & 63) << 25), __float_as_int(w));
        }
    }
}

// ---------------------------------------------------------------------------
// K4: fused edge-stream gather + variance + 64x64 GEMM.
// 16 half-warp streams walk contiguous edge chunks. Metas are loaded ONCE
// per 8-edge batch (coalesced, lanes sub<8) and distributed via shfl —
// no broadcast meta LDGs in the hot loop.
// ---------------------------------------------------------------------------
__global__ void __launch_bounds__(256, 4) gather_gemm_kernel(
    const float* __restrict__ input,
    const float* __restrict__ boundary,
    const float* __restrict__ relw,
    const float* __restrict__ W,
    const float* __restrict__ b,
    float* __restrict__ out)
{
    __shared__ float Ssh[64 * 68];     // s accumulators -> u (in place)
    __shared__ float Qsh[64 * 68];     // q accumulators -> reused as Wsh
    __shared__ float bsh[DIM];
    __shared__ float dinv[64];

    int tid  = threadIdx.x;
    int wid  = tid >> 5;
    int lane = tid & 31;
    int g    = lane >> 4;        // half-warp id within warp
    int sub  = lane & 15;        // float4 slice of 64-dim row
    int n0   = blockIdx.x * 64;

    // Init accumulators from boundary (coalesced)
    for (int i = tid; i < 64 * DIM; i += 256) {
        int nl = i >> 6, d = i & 63;
        int n  = n0 + nl;
        float bv = (n < NUM_NODE) ? __ldg(&boundary[(size_t)n0 * DIM + i]) : 0.0f;
        Ssh[nl * 68 + d] = bv;
        Qsh[nl * 68 + d] = bv * bv;
    }
    if (tid < 64) {
        int n = n0 + tid;
        if (n < NUM_NODE) {
            int st = __ldg(&g_off[n]);
            int en = __ldg(&g_off[n + 1]);
            dinv[tid] = 1.0f / ((float)(en - st) + 1.0f);
            g_count[n] = 0;      // self-clean for next call
        } else {
            dinv[tid] = 0.0f;
        }
    }
    if (tid < DIM) bsh[tid] = __ldg(&b[tid]);
    __syncthreads();

    // Edge range for this tile
    int nend   = (n0 + 64 < NUM_NODE) ? (n0 + 64) : NUM_NODE;
    int estart = __ldg(&g_off[n0]);
    int eend   = __ldg(&g_off[nend]);
    int cnt    = eend - estart;

    int h  = (wid << 1) | g;              // 0..15 stream id
    int C  = (cnt + 15) >> 4;             // chunk per stream
    int jb = estart + h * C;
    int je = jb + C; if (je > eend) je = eend;

    float4 sa = make_float4(0.f, 0.f, 0.f, 0.f);
    float4 qa = make_float4(0.f, 0.f, 0.f, 0.f);
    int cur = -1;

#define FLUSH() do {                                                     \
        float* sp_ = &Ssh[cur * 68 + (sub << 2)];                        \
        float* qp_ = &Qsh[cur * 68 + (sub << 2)];                        \
        atomicAdd(sp_ + 0, sa.x); atomicAdd(sp_ + 1, sa.y);              \
        atomicAdd(sp_ + 2, sa.z); atomicAdd(sp_ + 3, sa.w);              \
        atomicAdd(qp_ + 0, qa.x); atomicAdd(qp_ + 1, qa.y);              \
        atomicAdd(qp_ + 2, qa.z); atomicAdd(qp_ + 3, qa.w);              \
        sa = make_float4(0.f, 0.f, 0.f, 0.f);                            \
        qa = make_float4(0.f, 0.f, 0.f, 0.f);                            \
    } while (0)

#define ACC(a_, nl_) do {                                                \
        if ((nl_) != cur) { if (cur >= 0) FLUSH(); cur = (nl_); }        \
        sa.x += (a_).x; sa.y += (a_).y; sa.z += (a_).z; sa.w += (a_).w;  \
        qa.x += (a_).x * (a_).x; qa.y += (a_).y * (a_).y;                \
        qa.z += (a_).z * (a_).z; qa.w += (a_).w * (a_).w;                \
    } while (0)

    int      srcb  = g << 4;                    // lane base of this half-warp
    unsigned hmask = 0xFFFFu << srcb;           // half-warp shuffle mask

    int j = jb;
    if (j + 8 <= je) {
        // Prime: lanes sub<8 hold metas for the next 8 edges
        int2 mreg = make_int2(0, 0);
        if (sub < 8) mreg = __ldg(&g_meta[j + sub]);

        #pragma unroll 1
        for (; j + 8 <= je; j += 8) {
            int2 cm = mreg;
            int jn = j + 8;
            if (jn + 8 <= je && sub < 8) mreg = __ldg(&g_meta[jn + sub]);

            #pragma unroll
            for (int half = 0; half < 2; half++) {
                int sb = srcb + (half << 2);
                int k0 = __shfl_sync(hmask, cm.x, sb + 0);
                int k1 = __shfl_sync(hmask, cm.x, sb + 1);
                int k2 = __shfl_sync(hmask, cm.x, sb + 2);
                int k3 = __shfl_sync(hmask, cm.x, sb + 3);
                float w0 = __int_as_float(__shfl_sync(hmask, cm.y, sb + 0));
                float w1 = __int_as_float(__shfl_sync(hmask, cm.y, sb + 1));
                float w2 = __int_as_float(__shfl_sync(hmask, cm.y, sb + 2));
                float w3 = __int_as_float(__shfl_sync(hmask, cm.y, sb + 3));

                float4 x0 = __ldg((const float4*)(input + (size_t)(k0 & 0xFFFF) * DIM) + sub);
                float4 x1 = __ldg((const float4*)(input + (size_t)(k1 & 0xFFFF) * DIM) + sub);
                float4 x2 = __ldg((const float4*)(input + (size_t)(k2 & 0xFFFF) * DIM) + sub);
                float4 x3 = __ldg((const float4*)(input + (size_t)(k3 & 0xFFFF) * DIM) + sub);

                float4 r0 = __ldg((const float4*)(relw + (size_t)((k0 >> 16) & 0x1FF) * DIM) + sub);
                float4 r1 = __ldg((const float4*)(relw + (size_t)((k1 >> 16) & 0x1FF) * DIM) + sub);
                float4 r2 = __ldg((const float4*)(relw + (size_t)((k2 >> 16) & 0x1FF) * DIM) + sub);
                float4 r3 = __ldg((const float4*)(relw + (size_t)((k3 >> 16) & 0x1FF) * DIM) + sub);

                int nl0 = ((unsigned)k0) >> 25;
                int nl1 = ((unsigned)k1) >> 25;
                int nl2 = ((unsigned)k2) >> 25;
                int nl3 = ((unsigned)k3) >> 25;

                float4 a0, a1, a2, a3;
                a0.x = x0.x * r0.x * w0; a0.y = x0.y * r0.y * w0;
                a0.z = x0.z * r0.z * w0; a0.w = x0.w * r0.w * w0;
                a1.x = x1.x * r1.x * w1; a1.y = x1.y * r1.y * w1;
                a1.z = x1.z * r1.z * w1; a1.w = x1.w * r1.w * w1;
                a2.x = x2.x * r2.x * w2; a2.y = x2.y * r2.y * w2;
                a2.z = x2.z * r2.z * w2; a2.w = x2.w * r2.w * w2;
                a3.x = x3.x * r3.x * w3; a3.y = x3.y * r3.y * w3;
                a3.z = x3.z * r3.z * w3; a3.w = x3.w * r3.w * w3;

                if (nl0 == cur && nl1 == nl0 && nl2 == nl0 && nl3 == nl0) {
                    sa.x += a0.x + a1.x + a2.x + a3.x;
                    sa.y += a0.y + a1.y + a2.y + a3.y;
                    sa.z += a0.z + a1.z + a2.z + a3.z;
                    sa.w += a0.w + a1.w + a2.w + a3.w;
                    qa.x += a0.x * a0.x + a1.x * a1.x + a2.x * a2.x + a3.x * a3.x;
                    qa.y += a0.y * a0.y + a1.y * a1.y + a2.y * a2.y + a3.y * a3.y;
                    qa.z += a0.z * a0.z + a1.z * a1.z + a2.z * a2.z + a3.z * a3.z;
                    qa.w += a0.w * a0.w + a1.w * a1.w + a2.w * a2.w + a3.w * a3.w;
                } else {
                    ACC(a0, nl0); ACC(a1, nl1); ACC(a2, nl2); ACC(a3, nl3);
                }
            }
        }
    }

    // Remainder edges (scalar, broadcast loads — at most 7)
    for (; j < je; j++) {
        int2 m = __ldg(&g_meta[j]);
        int nl    = ((unsigned)m.x) >> 25;
        float w   = __int_as_float(m.y);
        float4 x  = __ldg((const float4*)(input + (size_t)(m.x & 0xFFFF) * DIM) + sub);
        float4 rr = __ldg((const float4*)(relw  + (size_t)((m.x >> 16) & 0x1FF) * DIM) + sub);
        float4 a;
        a.x = x.x * rr.x * w; a.y = x.y * rr.y * w;
        a.z = x.z * rr.z * w; a.w = x.w * rr.w * w;
        ACC(a, nl);
    }
    if (cur >= 0) FLUSH();
    __syncthreads();

    // ---- Variance: u = sqrt(max(q/d1 - (s/d1)^2, 1e-6)), in place into Ssh ----
    for (int i = tid; i < 64 * DIM; i += 256) {
        int nl = i >> 6, d = i & 63;
        float inv = dinv[nl];
        float s  = Ssh[nl * 68 + d];
        float q  = Qsh[nl * 68 + d];
        float sm = s * inv;
        Ssh[nl * 68 + d] = sqrtf(fmaxf(q * inv - sm * sm, 1e-6f));
    }
    __syncthreads();

    // ---- Load W transposed into Qsh storage (now free) ----
    float* Wsh = Qsh;
    for (int i = tid; i < DIM * DIM; i += 256) {
        int jj = i >> 6, d = i & 63;
        Wsh[d * DIM + jj] = __ldg(&W[i]);
    }
    __syncthreads();

    // ---- GEMM: out = u @ W^T + b ----
    int nl = tid >> 2;
    int j0 = (tid & 3) * 16;

    float acc[16];
    #pragma unroll
    for (int k = 0; k < 16; k++) acc[k] = bsh[j0 + k];

    #pragma unroll 4
    for (int d = 0; d < DIM; d++) {
        float u = Ssh[nl * 68 + d];
        const float4* wrow = (const float4*)&Wsh[d * DIM + j0];
        float4 w0 = wrow[0];
        float4 w1 = wrow[1];
        float4 w2 = wrow[2];
        float4 w3 = wrow[3];
        acc[0]  += u * w0.x;  acc[1]  += u * w0.y;
        acc[2]  += u * w0.z;  acc[3]  += u * w0.w;
        acc[4]  += u * w1.x;  acc[5]  += u * w1.y;
        acc[6]  += u * w1.z;  acc[7]  += u * w1.w;
        acc[8]  += u * w2.x;  acc[9]  += u * w2.y;
        acc[10] += u * w2.z;  acc[11] += u * w2.w;
        acc[12] += u * w3.x;  acc[13] += u * w3.y;
        acc[14] += u * w3.z;  acc[15] += u * w3.w;
    }

    int n = n0 + nl;
    if (n < NUM_NODE) {
        float4* op = (float4*)(out + (size_t)n * DIM + j0);
        op[0] = make_float4(acc[0],  acc[1],  acc[2],  acc[3]);
        op[1] = make_float4(acc[4],  acc[5],  acc[6],  acc[7]);
        op[2] = make_float4(acc[8],  acc[9],  acc[10], acc[11]);
        op[3] = make_float4(acc[12], acc[13], acc[14], acc[15]);
    }
}

// ---------------------------------------------------------------------------
// Launch. Inputs: input, boundary, edge_list, edge_weight, relation_weight, W, b
// ---------------------------------------------------------------------------
extern "C" void kernel_launch(void* const* d_in, const int* in_sizes, int n_in,
                              void* d_out, int out_size)
{
    const float* input    = (const float*)d_in[0];
    const float* boundary = (const float*)d_in[1];
    const int*   edges    = (const int*)  d_in[2];
    const float* eweight  = (const float*)d_in[3];
    const float* relw     = (const float*)d_in[4];
    const float* W        = (const float*)d_in[5];
    const float* b        = (const float*)d_in[6];
    float*       out      = (float*)d_out;

    hist_kernel<<<((NUM_EDGE + 3) / 4 + 255) / 256, 256>>>(edges);
    scan_kernel<<<1, SCAN_T>>>();
    scatter_kernel<<<((NUM_EDGE + 3) / 4 + 255) / 256, 256>>>(edges, eweight);
    gather_gemm_kernel<<<(NUM_NODE + 63) / 64, 256>>>(
        input, boundary, relw, W, b, out);
}